// round 1
// baseline (speedup 1.0000x reference)
#include <cuda_runtime.h>

#define W   30
#define TT  4096
#define FF  128
#define NS  (TT - W + 1)      // 4067 window starts
#define SEG 510               // 17 * 30 — every block does only full unrolled groups
#define NGROUPS (SEG / W)     // 17
#define EPSF 1e-4f

__global__ __launch_bounds__(FF)
void ts_zscore_kernel(const float* __restrict__ x, float* __restrict__ out)
{
    const int f = threadIdx.x;          // feature column
    const int b = blockIdx.x;           // batch
    int k0 = blockIdx.y * SEG;          // first window start handled by this block
    if (k0 > NS - SEG) k0 = NS - SEG;   // clamp: last block overlaps prior (same values)

    const float* __restrict__ xp = x   + ((size_t)b * TT + k0) * FF + f;
    float*       __restrict__ op = out + ((size_t)b * NS + k0) * FF + f;

    // Register ring buffer of the last 30 values (all indices static after unroll).
    float v[W];
    float s = 0.0f, s2 = 0.0f;

    // Prime with the first 29 values x[k0 .. k0+28].
#pragma unroll
    for (int i = 0; i < W - 1; ++i) {
        const float val = __ldg(xp + (size_t)i * FF);
        v[i] = val;
        s += val;
        s2 = fmaf(val, val, s2);
    }
    v[W - 1] = 0.0f;  // written before first read

    for (int g = 0; g < NGROUPS; ++g) {
        const int j = g * W;  // j % 30 == 0 always (keeps ring slot mapping static)
#pragma unroll
        for (int u = 0; u < W; ++u) {
            // New element entering the window for output (k0 + j + u): x[k0 + j + u + 29]
            const float nv = __ldg(xp + (size_t)(j + u + W - 1) * FF);
            v[(u + W - 1) % W] = nv;            // slot (j+u+29) % 30

            const float ss  = s + nv;           // sum over x[j+u .. j+u+29]
            const float ss2 = fmaf(nv, nv, s2);

            const float mean   = ss  * (1.0f / W);
            const float meansq = ss2 * (1.0f / W);
            float var = fmaf(-mean, mean, meansq);
            var = fmaxf(var, 0.0f);

            float stdv;
            asm("sqrt.approx.f32 %0, %1;" : "=f"(stdv) : "f"(var));
            const float r = __fdividef(nv - mean, stdv + EPSF);

            op[(size_t)(j + u) * FF] = r;

            // Retire the element leaving the window: x[k0 + j + u] at slot (j+u) % 30
            const float ov = v[u];
            s  = ss  - ov;
            s2 = fmaf(-ov, ov, ss2);
        }
        // Exact re-normalization from the ring to kill incremental FP drift.
        // After the group, slots 0..28 hold x[k0+j+30 .. k0+j+58] — exactly the
        // 29-element head of the next group's first window.
        float rs = 0.0f, rs2 = 0.0f;
#pragma unroll
        for (int i = 0; i < W - 1; ++i) {
            rs += v[i];
            rs2 = fmaf(v[i], v[i], rs2);
        }
        s = rs; s2 = rs2;
    }
}

extern "C" void kernel_launch(void* const* d_in, const int* in_sizes, int n_in,
                              void* d_out, int out_size)
{
    (void)n_in; (void)out_size;
    const float* x = (const float*)d_in[0];
    float* out = (float*)d_out;

    const int B = in_sizes[0] / (TT * FF);   // 64 for this problem
    dim3 grid(B, (NS + SEG - 1) / SEG);      // (64, 8)
    ts_zscore_kernel<<<grid, FF>>>(x, out);
}

// round 2
// speedup vs baseline: 1.3177x; 1.3177x over previous
#include <cuda_runtime.h>

#define W   30
#define TT  4096
#define FF  128
#define NS  (TT - W + 1)      // 4067 window starts
#define SEG 150               // 5 * 30 — every block does only full unrolled groups
#define NGROUPS (SEG / W)     // 5
#define EPSF 1e-4f

__global__ __launch_bounds__(FF)
void ts_zscore_kernel(const float* __restrict__ x, float* __restrict__ out)
{
    const int f = threadIdx.x;          // feature column
    const int b = blockIdx.x;           // batch
    int k0 = blockIdx.y * SEG;          // first window start handled by this block
    if (k0 > NS - SEG) k0 = NS - SEG;   // clamp: last block overlaps prior (same values)

    const float* __restrict__ xp = x   + ((size_t)b * TT + k0) * FF + f;
    float*       __restrict__ op = out + ((size_t)b * NS + k0) * FF + f;

    // Register ring buffer of the last 30 values (all indices static after unroll).
    float v[W];
    float s = 0.0f, s2 = 0.0f;

    // Prime with the first 29 values x[k0 .. k0+28].
#pragma unroll
    for (int i = 0; i < W - 1; ++i) {
        const float val = __ldg(xp + (size_t)i * FF);
        v[i] = val;
        s += val;
        s2 = fmaf(val, val, s2);
    }
    v[W - 1] = 0.0f;  // written before first read

#pragma unroll 1
    for (int g = 0; g < NGROUPS; ++g) {
        const int j = g * W;  // j % 30 == 0 always (keeps ring slot mapping static)
#pragma unroll
        for (int u = 0; u < W; ++u) {
            // New element entering the window for output (k0 + j + u): x[k0 + j + u + 29]
            const float nv = __ldg(xp + (size_t)(j + u + W - 1) * FF);
            v[(u + W - 1) % W] = nv;            // slot (j+u+29) % 30

            const float ss  = s + nv;           // sum over x[j+u .. j+u+29]
            const float ss2 = fmaf(nv, nv, s2);

            const float mean   = ss  * (1.0f / W);
            const float meansq = ss2 * (1.0f / W);
            float var = fmaf(-mean, mean, meansq);
            var = fmaxf(var, 0.0f);

            float stdv;
            asm("sqrt.approx.f32 %0, %1;" : "=f"(stdv) : "f"(var));
            const float r = __fdividef(nv - mean, stdv + EPSF);

            __stcs(op + (size_t)(j + u) * FF, r);  // streaming store: write-once data

            // Retire the element leaving the window: x[k0 + j + u] at slot (j+u) % 30
            const float ov = v[u];
            s  = ss  - ov;
            s2 = fmaf(-ov, ov, ss2);
        }
        // Exact re-normalization from the ring to kill incremental FP drift.
        // After the group, slots 0..28 hold x[k0+j+30 .. k0+j+58] — exactly the
        // 29-element head of the next group's first window.
        float rs = 0.0f, rs2 = 0.0f;
#pragma unroll
        for (int i = 0; i < W - 1; ++i) {
            rs += v[i];
            rs2 = fmaf(v[i], v[i], rs2);
        }
        s = rs; s2 = rs2;
    }
}

extern "C" void kernel_launch(void* const* d_in, const int* in_sizes, int n_in,
                              void* d_out, int out_size)
{
    (void)n_in; (void)out_size;
    const float* x = (const float*)d_in[0];
    float* out = (float*)d_out;

    const int B = in_sizes[0] / (TT * FF);   // 64 for this problem
    dim3 grid(B, (NS + SEG - 1) / SEG);      // (64, 28)
    ts_zscore_kernel<<<grid, FF>>>(x, out);
}

// round 3
// speedup vs baseline: 1.4235x; 1.0804x over previous
#include <cuda_runtime.h>

#define W   30
#define TT  4096
#define FF  128
#define NS  (TT - W + 1)      // 4067 window starts
#define SEG 150               // 5 * 30
#define NGROUPS (SEG / W)     // 5
#define EPSF 1e-4f

__global__ __launch_bounds__(FF)
void ts_zscore_kernel(const float* __restrict__ x, float* __restrict__ out)
{
    const int f = threadIdx.x;          // feature column
    const int b = blockIdx.x;           // batch
    int k0 = blockIdx.y * SEG;          // first window start handled by this block
    if (k0 > NS - SEG) k0 = NS - SEG;   // clamp: last block overlaps prior (same values)

    const float* __restrict__ xp = x   + ((size_t)b * TT + k0) * FF + f;
    float*       __restrict__ op = out + ((size_t)b * NS + k0) * FF + f;

    float s = 0.0f, s2 = 0.0f;

    // Prime with the first 29 values x[k0 .. k0+28] (also warms L1 for the
    // ov re-loads below).
#pragma unroll
    for (int i = 0; i < W - 1; ++i) {
        const float val = __ldg(xp + (size_t)i * FF);
        s += val;
        s2 = fmaf(val, val, s2);
    }

#pragma unroll 1
    for (int g = 0; g < NGROUPS; ++g) {
#pragma unroll
        for (int u = 0; u < W; ++u) {
            // New element entering the window for output u: x[.. + u + 29]
            const float nv = __ldg(xp + (size_t)(u + W - 1) * FF);

            const float ss  = s + nv;           // window sum
            const float ss2 = fmaf(nv, nv, s2);

            const float mean   = ss  * (1.0f / W);
            const float meansq = ss2 * (1.0f / W);
            float var = fmaf(-mean, mean, meansq);
            var = fmaxf(var, 0.0f);

            float stdv;
            asm("sqrt.approx.f32 %0, %1;" : "=f"(stdv) : "f"(var));
            const float r = __fdividef(nv - mean, stdv + EPSF);

            __stcs(op + (size_t)u * FF, r);     // streaming store: write-once data

            // Element leaving the window: re-load x[.. + u] — it was this
            // thread's nv 29 iterations ago, so it's an L1/L2 hit.
            const float ov = __ldg(xp + (size_t)u * FF);
            s  = ss  - ov;
            s2 = fmaf(-ov, ov, ss2);
        }
        xp += (size_t)W * FF;
        op += (size_t)W * FF;
    }
}

extern "C" void kernel_launch(void* const* d_in, const int* in_sizes, int n_in,
                              void* d_out, int out_size)
{
    (void)n_in; (void)out_size;
    const float* x = (const float*)d_in[0];
    float* out = (float*)d_out;

    const int B = in_sizes[0] / (TT * FF);   // 64 for this problem
    dim3 grid(B, (NS + SEG - 1) / SEG);      // (64, 28)
    ts_zscore_kernel<<<grid, FF>>>(x, out);
}